// round 12
// baseline (speedup 1.0000x reference)
#include <cuda_runtime.h>
#include <math.h>

#define MAXN 10000
#define MAXE 320000

// Scratch (__device__ globals per allocation-free rule)
__device__ float4 g_y4[MAXN * 64];    // [node][u] = (y0, y1x, y1y, y1z), scale 1/8 folded
__device__ float  g_agg[MAXN * 512];  // reference concat layout, LIN2S (1/64) folded
__device__ float4 g_erec[MAXE * 4];   // packed CSR edge record: [sh | h0..3 | h4..7 | src,pad]
__device__ int    g_deg[MAXN];        // zero-invariant between calls (scan re-zeroes)
__device__ int    g_row[MAXN + 1];
__device__ int    g_cursor[MAXN];

#define INV_SQRT8 0.35355339059327373f
#define INV_SQRT3 0.5773502691896258f
#define LOG2F_C   0.6931471805599453f
#define LIN2S     0.015625f   // 1/(sqrt(32)*sqrt(128))
#define SCN       0.0625f     // 1/sqrt(64*4)

// ---------------------------------------------------------------------------
__global__ void count_kernel(const int* __restrict__ eidx, int E) {
    int e = blockIdx.x * blockDim.x + threadIdx.x;
    if (e < E) atomicAdd(&g_deg[eidx[e]], 1);
}

// Single-block scan g_deg -> g_row, g_cursor; re-zeroes g_deg for the next call.
__global__ void scan_kernel(int n) {
    __shared__ int part[1024];
    int tid = threadIdx.x;
    int IT = (n + 1023) >> 10;          // <=16 for n<=16384
    int base = tid * IT;
    int degs[16];
    int s = 0;
    for (int i = 0; i < IT; ++i) {
        int idx = base + i;
        degs[i] = (idx < n) ? g_deg[idx] : 0;
        s += degs[i];
    }
    part[tid] = s;
    __syncthreads();
    for (int off = 1; off < 1024; off <<= 1) {
        int v = (tid >= off) ? part[tid - off] : 0;
        __syncthreads();
        part[tid] += v;
        __syncthreads();
    }
    int run = part[tid] - s;
    for (int i = 0; i < IT; ++i) {
        int idx = base + i;
        if (idx < n) {
            g_row[idx] = run;
            g_cursor[idx] = run;
            run += degs[i];
            g_deg[idx] = 0;             // restore zero-invariant
        }
    }
    if (tid == 1023) g_row[n] = part[1023];
}

// ---------------------------------------------------------------------------
// Fused launch: blocks [0, sb) = scatter_h (edge MLP + packed-record CSR scatter);
//               blocks [sb, ...) = node-pre GEMMs (independent outputs).
__global__ void fused_scatter_pre_kernel(const int* __restrict__ eidx,
                                         const float* __restrict__ eemb,
                                         const float* __restrict__ eattr,
                                         const float* __restrict__ Wfc1,
                                         const float* __restrict__ nf,
                                         const float* __restrict__ Wl10,
                                         const float* __restrict__ Wl11,
                                         int E, int n, int sb, int nb0) {
    __shared__ __align__(16) float sIn[32 * 64];   // pre: inputs (aliases scatter's sW1)
    __shared__ __align__(16) float sW[64 * 64];    // pre: weights
    int tid = threadIdx.x;

    if (blockIdx.x < sb) {
        // ----- scatter_h part -----
        float* sW1 = sIn;   // 64 floats
        if (tid < 64) sW1[tid] = Wfc1[tid];
        __syncthreads();
        int e = blockIdx.x * 256 + tid;
        if (e >= E) return;

        int dst = __ldg(eidx + e);
        int src = __ldg(eidx + E + e);
        int pos = atomicAdd(&g_cursor[dst], 1);

        float4 sh = __ldg((const float4*)(eattr + (size_t)e * 4));
        float4 e0 = *(const float4*)(eemb + (size_t)e * 8);
        float4 e1 = *(const float4*)(eemb + (size_t)e * 8 + 4);
        float emb[8] = {e0.x, e0.y, e0.z, e0.w, e1.x, e1.y, e1.z, e1.w};
        float h[8];
        #pragma unroll
        for (int j = 0; j < 8; ++j) {
            float z = 0.f;
            #pragma unroll
            for (int k = 0; k < 8; ++k) z = fmaf(emb[k], sW1[k * 8 + j], z);
            z *= INV_SQRT8;
            float sp = (z > 20.f) ? z : log1pf(__expf(z));
            h[j] = (sp - LOG2F_C) * INV_SQRT8;
        }

        float4* rp = g_erec + (size_t)pos * 4;
        rp[0] = sh;
        rp[1] = make_float4(h[0], h[1], h[2], h[3]);
        rp[2] = make_float4(h[4], h[5], h[6], h[7]);
        rp[3] = make_float4(__int_as_float(src), 0.f, 0.f, 0.f);
        return;
    }

    // ----- node pre GEMM part -----
    int bx = blockIdx.x - sb;
    int v = tid & 63, rgrp = tid >> 6;
    int mode = (bx >= nb0) ? 1 : 0;
    int blk = mode ? (bx - nb0) : bx;
    int rows = mode ? 3 * n : n;
    int rbase = blk * 32;
    const float* W = mode ? Wl11 : Wl10;

    for (int i = tid; i < 4096; i += 256) sW[i] = W[i];
    for (int i = tid; i < 2048; i += 256) {
        int row = i >> 6, k = i & 63;
        int rg = rbase + row;
        float val = 0.f;
        if (rg < rows) {
            if (mode == 0) val = nf[(size_t)rg * 256 + k];
            else {
                int node = rg / 3, m = rg % 3;
                val = nf[(size_t)node * 256 + 64 + k * 3 + m];
            }
        }
        sIn[i] = val;
    }
    __syncthreads();

    float acc[8] = {0.f, 0.f, 0.f, 0.f, 0.f, 0.f, 0.f, 0.f};
    for (int kk = 0; kk < 64; kk += 4) {
        float w0 = sW[(kk + 0) * 64 + v];
        float w1 = sW[(kk + 1) * 64 + v];
        float w2 = sW[(kk + 2) * 64 + v];
        float w3 = sW[(kk + 3) * 64 + v];
        #pragma unroll
        for (int r = 0; r < 8; ++r) {
            const float4 in4 = *(const float4*)(sIn + (rgrp * 8 + r) * 64 + kk);
            acc[r] = fmaf(in4.x, w0, fmaf(in4.y, w1, fmaf(in4.z, w2, fmaf(in4.w, w3, acc[r]))));
        }
    }
    float* gy = (float*)g_y4;
    #pragma unroll
    for (int r = 0; r < 8; ++r) {
        int rg = rbase + rgrp * 8 + r;
        if (rg >= rows) continue;
        float val = acc[r] * 0.125f;
        if (mode == 0) gy[((size_t)rg * 64 + v) * 4 + 0] = val;
        else {
            int node = rg / 3, m = rg % 3;
            gy[((size_t)node * 64 + v) * 4 + 1 + m] = val;
        }
    }
}

// ---------------------------------------------------------------------------
// Aggregation: block per node, 4 groups x 64 threads, register weights,
// packed-record stream + single float4 y gather per edge. No atomics.
__global__ void __launch_bounds__(256) agg_kernel(const float* __restrict__ Wfc2,
                           int E, int n) {
    __shared__ float spart[4 * 512];
    int tid = threadIdx.x;
    int u = tid & 63, grp = tid >> 6;

    // Per-thread weight columns u, 64+u, 128+u, 192+u for j=0..7 (coalesced loads, once).
    float wA[8], wB[8], wC[8], wD[8];
    #pragma unroll
    for (int j = 0; j < 8; ++j) {
        const float* r = Wfc2 + j * 256;
        wA[j] = __ldg(r + u);
        wB[j] = __ldg(r + 64 + u);
        wC[j] = __ldg(r + 128 + u);
        wD[j] = __ldg(r + 192 + u);
    }

    int node = blockIdx.x;
    int rs = g_row[node], re = g_row[node + 1];

    float a0 = 0.f, a1 = 0.f, a2 = 0.f, a3 = 0.f, a4 = 0.f, a5 = 0.f, a6 = 0.f, a7 = 0.f;

    for (int i = rs + grp; i < re; i += 4) {
        const float4* rp = g_erec + (size_t)i * 4;   // sequential per node, uniform per group
        float4 sh = __ldg(rp);
        float4 h0 = __ldg(rp + 1);
        float4 h1 = __ldg(rp + 2);
        int src = __float_as_int(__ldg((const float*)(rp + 3)));

        float4 y4 = __ldg(g_y4 + (size_t)src * 64 + u);  // one LDG.128: (y0,y1x,y1y,y1z)
        float xs0 = y4.x, x1x = y4.y, x1y = y4.z, x1z = y4.w;

        float w1 = fmaf(h0.x, wA[0], fmaf(h0.y, wA[1], fmaf(h0.z, wA[2], fmaf(h0.w, wA[3],
                   fmaf(h1.x, wA[4], fmaf(h1.y, wA[5], fmaf(h1.z, wA[6], h1.w * wA[7])))))));
        float w2 = fmaf(h0.x, wB[0], fmaf(h0.y, wB[1], fmaf(h0.z, wB[2], fmaf(h0.w, wB[3],
                   fmaf(h1.x, wB[4], fmaf(h1.y, wB[5], fmaf(h1.z, wB[6], h1.w * wB[7])))))));
        float w3 = fmaf(h0.x, wC[0], fmaf(h0.y, wC[1], fmaf(h0.z, wC[2], fmaf(h0.w, wC[3],
                   fmaf(h1.x, wC[4], fmaf(h1.y, wC[5], fmaf(h1.z, wC[6], h1.w * wC[7])))))));
        float w4 = fmaf(h0.x, wD[0], fmaf(h0.y, wD[1], fmaf(h0.z, wD[2], fmaf(h0.w, wD[3],
                   fmaf(h1.x, wD[4], fmaf(h1.y, wD[5], fmaf(h1.z, wD[6], h1.w * wD[7])))))));

        float dotv = fmaf(x1x, sh.y, fmaf(x1y, sh.z, x1z * sh.w));
        float a2c = w2 * xs0;
        float a3c = w3 * sh.x;
        a0 = fmaf(w1 * xs0, sh.x, a0);
        a1 = fmaf(w4 * INV_SQRT3, dotv, a1);
        a2 = fmaf(a2c, sh.y, a2);
        a3 = fmaf(a2c, sh.z, a3);
        a4 = fmaf(a2c, sh.w, a4);
        a5 = fmaf(a3c, x1x, a5);
        a6 = fmaf(a3c, x1y, a6);
        a7 = fmaf(a3c, x1z, a7);
    }

    float* sp = spart + grp * 512;
    sp[u] = a0;
    sp[64 + u] = a1;
    sp[128 + 3 * u + 0] = a2;
    sp[128 + 3 * u + 1] = a3;
    sp[128 + 3 * u + 2] = a4;
    sp[320 + 3 * u + 0] = a5;
    sp[320 + 3 * u + 1] = a6;
    sp[320 + 3 * u + 2] = a7;
    __syncthreads();

    float* arow = g_agg + (size_t)node * 512;
    for (int idx = tid; idx < 512; idx += 256)
        arow[idx] = (spart[idx] + spart[512 + idx] + spart[1024 + idx] + spart[1536 + idx]) * LIN2S;
}

// ---------------------------------------------------------------------------
// Node post GEMM, K=384 (3 chunks of 128): [agg_part | attrs (x) x] @ [W_lin2 ; W_sc].
__global__ void post_gemm_kernel(const float* __restrict__ nf,
                                 const float* __restrict__ attrs,
                                 const float* __restrict__ Wl20,
                                 const float* __restrict__ Wl21,
                                 const float* __restrict__ Wsc0,
                                 const float* __restrict__ Wsc1,
                                 float* __restrict__ out,
                                 int n, int nb0) {
    __shared__ __align__(16) float sIn[32 * 128];   // 16 KB
    __shared__ __align__(16) float sW[128 * 64];    // 32 KB
    int tid = threadIdx.x;
    int v = tid & 63, rgrp = tid >> 6;
    int mode = (blockIdx.x >= nb0) ? 1 : 0;
    int blk = mode ? (blockIdx.x - nb0) : blockIdx.x;
    int rows = mode ? 3 * n : n;
    int rbase = blk * 32;
    const float* Wlin = mode ? Wl21 : Wl20;
    const float* Wsc  = mode ? Wsc1 : Wsc0;

    float acc[8] = {0.f, 0.f, 0.f, 0.f, 0.f, 0.f, 0.f, 0.f};

    for (int c = 0; c < 3; ++c) {
        for (int i = tid; i < 8192; i += 256) {
            int kk = i >> 6, vv = i & 63;
            int k = c * 128 + kk;
            float w;
            if (k < 128) w = Wlin[k * 64 + vv];
            else {
                int t2 = k - 128, a = t2 >> 6, uu = t2 & 63;
                w = Wsc[uu * 256 + a * 64 + vv];
            }
            sW[i] = w;
        }
        for (int i = tid; i < 4096; i += 256) {
            int row = i >> 7, kk = i & 127;
            int rg = rbase + row;
            int k = c * 128 + kk;
            float val = 0.f;
            if (rg < rows) {
                if (mode == 0) {
                    if (k < 128) val = g_agg[(size_t)rg * 512 + k];
                    else {
                        int t2 = k - 128, a = t2 >> 6, uu = t2 & 63;
                        val = attrs[(size_t)rg * 4 + a] * nf[(size_t)rg * 256 + uu] * SCN;
                    }
                } else {
                    int node = rg / 3, m = rg % 3;
                    if (k < 128) val = g_agg[(size_t)node * 512 + 128 + k * 3 + m];
                    else {
                        int t2 = k - 128, a = t2 >> 6, uu = t2 & 63;
                        val = attrs[(size_t)node * 4 + a] * nf[(size_t)node * 256 + 64 + uu * 3 + m] * SCN;
                    }
                }
            }
            sIn[i] = val;
        }
        __syncthreads();

        for (int kk = 0; kk < 128; kk += 4) {
            float w0 = sW[(kk + 0) * 64 + v];
            float w1 = sW[(kk + 1) * 64 + v];
            float w2 = sW[(kk + 2) * 64 + v];
            float w3 = sW[(kk + 3) * 64 + v];
            #pragma unroll
            for (int r = 0; r < 8; ++r) {
                const float4 in4 = *(const float4*)(sIn + (rgrp * 8 + r) * 128 + kk);
                acc[r] = fmaf(in4.x, w0, fmaf(in4.y, w1, fmaf(in4.z, w2, fmaf(in4.w, w3, acc[r]))));
            }
        }
        __syncthreads();
    }

    #pragma unroll
    for (int r = 0; r < 8; ++r) {
        int rg = rbase + rgrp * 8 + r;
        if (rg >= rows) continue;
        if (mode == 0) out[(size_t)rg * 256 + v] = acc[r];
        else {
            int node = rg / 3, m = rg % 3;
            out[(size_t)node * 256 + 64 + v * 3 + m] = acc[r];
        }
    }
}

// ---------------------------------------------------------------------------
extern "C" void kernel_launch(void* const* d_in, const int* in_sizes, int n_in,
                              void* d_out, int out_size) {
    const float* nf    = (const float*)d_in[0];
    const float* attrs = (const float*)d_in[1];
    const float* ea    = (const float*)d_in[2];
    const float* ee    = (const float*)d_in[3];
    const int*   ei    = (const int*)d_in[4];
    const float* Wl10  = (const float*)d_in[5];
    const float* Wl11  = (const float*)d_in[6];
    const float* Wfc1  = (const float*)d_in[7];
    const float* Wfc2  = (const float*)d_in[8];
    const float* Wl20  = (const float*)d_in[9];
    const float* Wl21  = (const float*)d_in[10];
    const float* Wsc0  = (const float*)d_in[11];
    const float* Wsc1  = (const float*)d_in[12];
    float* out = (float*)d_out;

    int n = in_sizes[0] / 256;
    int E = in_sizes[2] / 4;

    // launch 0: degree count (g_deg starts zero: zero-init + scan re-zeroes)
    count_kernel<<<(E + 255) / 256, 256>>>(ei, E);
    // launch 1: scan -> row/cursor, re-zero g_deg
    scan_kernel<<<1, 1024>>>(n);
    // launch 2: fused scatter_h + node-pre
    int sb = (E + 255) / 256;
    int pre_nb0 = (n + 31) / 32, pre_nb1 = (3 * n + 31) / 32;
    fused_scatter_pre_kernel<<<sb + pre_nb0 + pre_nb1, 256>>>(
        ei, ee, ea, Wfc1, nf, Wl10, Wl11, E, n, sb, pre_nb0);
    // launch 3: aggregation (profiled slot)
    agg_kernel<<<n, 256>>>(Wfc2, E, n);
    // launch 4: node post
    int post_nb0 = (n + 31) / 32, post_nb1 = (3 * n + 31) / 32;
    post_gemm_kernel<<<post_nb0 + post_nb1, 256>>>(nf, attrs, Wl20, Wl21, Wsc0, Wsc1, out, n, post_nb0);
}

// round 13
// speedup vs baseline: 1.0804x; 1.0804x over previous
#include <cuda_runtime.h>
#include <math.h>

#define MAXN 10000
#define MAXE 320000

// Scratch (__device__ globals per allocation-free rule)
__device__ float4 g_y4[MAXN * 64];    // [node][u] = (y0, y1x, y1y, y1z), scale 1/8 folded
__device__ float  g_agg[MAXN * 512];  // reference concat layout, LIN2S (1/64) folded
__device__ float4 g_erec[MAXE * 4];   // packed CSR edge record: [sh | h0..3 | h4..7 | src,pad]
__device__ int    g_deg[MAXN];        // zero-invariant between calls (scan re-zeroes)
__device__ int    g_row[MAXN + 1];
__device__ int    g_cursor[MAXN];

#define INV_SQRT8 0.35355339059327373f
#define INV_SQRT3 0.5773502691896258f
#define LOG2F_C   0.6931471805599453f
#define LIN2S     0.015625f   // 1/(sqrt(32)*sqrt(128))
#define SCN       0.0625f     // 1/sqrt(64*4)

// ---------------------------------------------------------------------------
__global__ void count_kernel(const int* __restrict__ eidx, int E) {
    int e = blockIdx.x * blockDim.x + threadIdx.x;
    if (e < E) atomicAdd(&g_deg[eidx[e]], 1);
}

// Single-block scan g_deg -> g_row, g_cursor; re-zeroes g_deg for the next call.
__global__ void scan_kernel(int n) {
    __shared__ int part[1024];
    int tid = threadIdx.x;
    int IT = (n + 1023) >> 10;
    int base = tid * IT;
    int degs[16];
    int s = 0;
    for (int i = 0; i < IT; ++i) {
        int idx = base + i;
        degs[i] = (idx < n) ? g_deg[idx] : 0;
        s += degs[i];
    }
    part[tid] = s;
    __syncthreads();
    for (int off = 1; off < 1024; off <<= 1) {
        int v = (tid >= off) ? part[tid - off] : 0;
        __syncthreads();
        part[tid] += v;
        __syncthreads();
    }
    int run = part[tid] - s;
    for (int i = 0; i < IT; ++i) {
        int idx = base + i;
        if (idx < n) {
            g_row[idx] = run;
            g_cursor[idx] = run;
            run += degs[i];
            g_deg[idx] = 0;             // restore zero-invariant
        }
    }
    if (tid == 1023) g_row[n] = part[1023];
}

// Fused: per-edge MLP hidden layer h + CSR scatter of the PACKED 64B record.
__global__ void scatter_h_kernel(const int* __restrict__ eidx,
                                 const float* __restrict__ eemb,
                                 const float* __restrict__ eattr,
                                 const float* __restrict__ Wfc1,
                                 int E) {
    __shared__ float sW1[64];
    int tid = threadIdx.x;
    if (tid < 64) sW1[tid] = Wfc1[tid];
    __syncthreads();
    int e = blockIdx.x * blockDim.x + tid;
    if (e >= E) return;

    // Kick off the atomic early; compute h underneath its latency.
    int dst = __ldg(eidx + e);
    int src = __ldg(eidx + E + e);
    int pos = atomicAdd(&g_cursor[dst], 1);

    float4 sh = __ldg((const float4*)(eattr + (size_t)e * 4));
    float4 e0 = *(const float4*)(eemb + (size_t)e * 8);
    float4 e1 = *(const float4*)(eemb + (size_t)e * 8 + 4);
    float emb[8] = {e0.x, e0.y, e0.z, e0.w, e1.x, e1.y, e1.z, e1.w};
    float h[8];
    #pragma unroll
    for (int j = 0; j < 8; ++j) {
        float z = 0.f;
        #pragma unroll
        for (int k = 0; k < 8; ++k) z = fmaf(emb[k], sW1[k * 8 + j], z);
        z *= INV_SQRT8;
        float sp = (z > 20.f) ? z : log1pf(__expf(z));
        h[j] = (sp - LOG2F_C) * INV_SQRT8;
    }

    float4* rp = g_erec + (size_t)pos * 4;
    rp[0] = sh;
    rp[1] = make_float4(h[0], h[1], h[2], h[3]);
    rp[2] = make_float4(h[4], h[5], h[6], h[7]);
    rp[3] = make_float4(__int_as_float(src), 0.f, 0.f, 0.f);
}

// ---------------------------------------------------------------------------
// Node pre GEMMs, K=64 (both modes in one launch). Writes float4 g_y4 layout.
__global__ void pre_gemm_kernel(const float* __restrict__ nf,
                                const float* __restrict__ Wl10,
                                const float* __restrict__ Wl11,
                                int n, int nb0) {
    __shared__ __align__(16) float sIn[32 * 64];
    __shared__ __align__(16) float sW[64 * 64];
    int tid = threadIdx.x;
    int v = tid & 63, rgrp = tid >> 6;
    int mode = (blockIdx.x >= nb0) ? 1 : 0;
    int blk = mode ? (blockIdx.x - nb0) : blockIdx.x;
    int rows = mode ? 3 * n : n;
    int rbase = blk * 32;
    const float* W = mode ? Wl11 : Wl10;

    for (int i = tid; i < 4096; i += 256) sW[i] = W[i];
    for (int i = tid; i < 2048; i += 256) {
        int row = i >> 6, k = i & 63;
        int rg = rbase + row;
        float val = 0.f;
        if (rg < rows) {
            if (mode == 0) val = nf[(size_t)rg * 256 + k];
            else {
                int node = rg / 3, m = rg % 3;
                val = nf[(size_t)node * 256 + 64 + k * 3 + m];
            }
        }
        sIn[i] = val;
    }
    __syncthreads();

    float acc[8] = {0.f, 0.f, 0.f, 0.f, 0.f, 0.f, 0.f, 0.f};
    for (int kk = 0; kk < 64; kk += 4) {
        float w0 = sW[(kk + 0) * 64 + v];
        float w1 = sW[(kk + 1) * 64 + v];
        float w2 = sW[(kk + 2) * 64 + v];
        float w3 = sW[(kk + 3) * 64 + v];
        #pragma unroll
        for (int r = 0; r < 8; ++r) {
            const float4 in4 = *(const float4*)(sIn + (rgrp * 8 + r) * 64 + kk);
            acc[r] = fmaf(in4.x, w0, fmaf(in4.y, w1, fmaf(in4.z, w2, fmaf(in4.w, w3, acc[r]))));
        }
    }
    float* gy = (float*)g_y4;
    #pragma unroll
    for (int r = 0; r < 8; ++r) {
        int rg = rbase + rgrp * 8 + r;
        if (rg >= rows) continue;
        float val = acc[r] * 0.125f;
        if (mode == 0) gy[((size_t)rg * 64 + v) * 4 + 0] = val;
        else {
            int node = rg / 3, m = rg % 3;
            gy[((size_t)node * 64 + v) * 4 + 1 + m] = val;
        }
    }
}

// ---------------------------------------------------------------------------
// Aggregation v3: 64-thread block per node, thread owns channel u end-to-end.
// No smem, no barriers, no reduction; full-deg loop per thread. No atomics.
__global__ void __launch_bounds__(64) agg_kernel(const float* __restrict__ Wfc2, int n) {
    int u = threadIdx.x;
    int node = blockIdx.x;

    // Per-thread weight columns u, 64+u, 128+u, 192+u for j=0..7 (coalesced loads, once).
    float wA[8], wB[8], wC[8], wD[8];
    #pragma unroll
    for (int j = 0; j < 8; ++j) {
        const float* r = Wfc2 + j * 256;
        wA[j] = __ldg(r + u);
        wB[j] = __ldg(r + 64 + u);
        wC[j] = __ldg(r + 128 + u);
        wD[j] = __ldg(r + 192 + u);
    }

    int rs = g_row[node], re = g_row[node + 1];

    float a0 = 0.f, a1 = 0.f, a2 = 0.f, a3 = 0.f, a4 = 0.f, a5 = 0.f, a6 = 0.f, a7 = 0.f;

    for (int i = rs; i < re; ++i) {
        const float4* rp = g_erec + (size_t)i * 4;   // sequential per node, uniform per block
        float4 sh = __ldg(rp);
        float4 h0 = __ldg(rp + 1);
        float4 h1 = __ldg(rp + 2);
        int src = __float_as_int(__ldg((const float*)(rp + 3)));

        float4 y4 = __ldg(g_y4 + (size_t)src * 64 + u);  // one LDG.128: (y0,y1x,y1y,y1z)
        float xs0 = y4.x, x1x = y4.y, x1y = y4.z, x1z = y4.w;

        float w1 = fmaf(h0.x, wA[0], fmaf(h0.y, wA[1], fmaf(h0.z, wA[2], fmaf(h0.w, wA[3],
                   fmaf(h1.x, wA[4], fmaf(h1.y, wA[5], fmaf(h1.z, wA[6], h1.w * wA[7])))))));
        float w2 = fmaf(h0.x, wB[0], fmaf(h0.y, wB[1], fmaf(h0.z, wB[2], fmaf(h0.w, wB[3],
                   fmaf(h1.x, wB[4], fmaf(h1.y, wB[5], fmaf(h1.z, wB[6], h1.w * wB[7])))))));
        float w3 = fmaf(h0.x, wC[0], fmaf(h0.y, wC[1], fmaf(h0.z, wC[2], fmaf(h0.w, wC[3],
                   fmaf(h1.x, wC[4], fmaf(h1.y, wC[5], fmaf(h1.z, wC[6], h1.w * wC[7])))))));
        float w4 = fmaf(h0.x, wD[0], fmaf(h0.y, wD[1], fmaf(h0.z, wD[2], fmaf(h0.w, wD[3],
                   fmaf(h1.x, wD[4], fmaf(h1.y, wD[5], fmaf(h1.z, wD[6], h1.w * wD[7])))))));

        float dotv = fmaf(x1x, sh.y, fmaf(x1y, sh.z, x1z * sh.w));
        float a2c = w2 * xs0;
        float a3c = w3 * sh.x;
        a0 = fmaf(w1 * xs0, sh.x, a0);
        a1 = fmaf(w4 * INV_SQRT3, dotv, a1);
        a2 = fmaf(a2c, sh.y, a2);
        a3 = fmaf(a2c, sh.z, a3);
        a4 = fmaf(a2c, sh.w, a4);
        a5 = fmaf(a3c, x1x, a5);
        a6 = fmaf(a3c, x1y, a6);
        a7 = fmaf(a3c, x1z, a7);
    }

    float* arow = g_agg + (size_t)node * 512;
    arow[u]               = a0 * LIN2S;
    arow[64 + u]          = a1 * LIN2S;
    arow[128 + 3 * u + 0] = a2 * LIN2S;
    arow[128 + 3 * u + 1] = a3 * LIN2S;
    arow[128 + 3 * u + 2] = a4 * LIN2S;
    arow[320 + 3 * u + 0] = a5 * LIN2S;
    arow[320 + 3 * u + 1] = a6 * LIN2S;
    arow[320 + 3 * u + 2] = a7 * LIN2S;
}

// ---------------------------------------------------------------------------
// Node post GEMM, K=384 (3 chunks of 128): [agg_part | attrs (x) x] @ [W_lin2 ; W_sc].
__global__ void post_gemm_kernel(const float* __restrict__ nf,
                                 const float* __restrict__ attrs,
                                 const float* __restrict__ Wl20,
                                 const float* __restrict__ Wl21,
                                 const float* __restrict__ Wsc0,
                                 const float* __restrict__ Wsc1,
                                 float* __restrict__ out,
                                 int n, int nb0) {
    __shared__ __align__(16) float sIn[32 * 128];   // 16 KB
    __shared__ __align__(16) float sW[128 * 64];    // 32 KB
    int tid = threadIdx.x;
    int v = tid & 63, rgrp = tid >> 6;
    int mode = (blockIdx.x >= nb0) ? 1 : 0;
    int blk = mode ? (blockIdx.x - nb0) : blockIdx.x;
    int rows = mode ? 3 * n : n;
    int rbase = blk * 32;
    const float* Wlin = mode ? Wl21 : Wl20;
    const float* Wsc  = mode ? Wsc1 : Wsc0;

    float acc[8] = {0.f, 0.f, 0.f, 0.f, 0.f, 0.f, 0.f, 0.f};

    for (int c = 0; c < 3; ++c) {
        for (int i = tid; i < 8192; i += 256) {
            int kk = i >> 6, vv = i & 63;
            int k = c * 128 + kk;
            float w;
            if (k < 128) w = Wlin[k * 64 + vv];
            else {
                int t2 = k - 128, a = t2 >> 6, uu = t2 & 63;
                w = Wsc[uu * 256 + a * 64 + vv];
            }
            sW[i] = w;
        }
        for (int i = tid; i < 4096; i += 256) {
            int row = i >> 7, kk = i & 127;
            int rg = rbase + row;
            int k = c * 128 + kk;
            float val = 0.f;
            if (rg < rows) {
                if (mode == 0) {
                    if (k < 128) val = g_agg[(size_t)rg * 512 + k];
                    else {
                        int t2 = k - 128, a = t2 >> 6, uu = t2 & 63;
                        val = attrs[(size_t)rg * 4 + a] * nf[(size_t)rg * 256 + uu] * SCN;
                    }
                } else {
                    int node = rg / 3, m = rg % 3;
                    if (k < 128) val = g_agg[(size_t)node * 512 + 128 + k * 3 + m];
                    else {
                        int t2 = k - 128, a = t2 >> 6, uu = t2 & 63;
                        val = attrs[(size_t)node * 4 + a] * nf[(size_t)node * 256 + 64 + uu * 3 + m] * SCN;
                    }
                }
            }
            sIn[i] = val;
        }
        __syncthreads();

        for (int kk = 0; kk < 128; kk += 4) {
            float w0 = sW[(kk + 0) * 64 + v];
            float w1 = sW[(kk + 1) * 64 + v];
            float w2 = sW[(kk + 2) * 64 + v];
            float w3 = sW[(kk + 3) * 64 + v];
            #pragma unroll
            for (int r = 0; r < 8; ++r) {
                const float4 in4 = *(const float4*)(sIn + (rgrp * 8 + r) * 128 + kk);
                acc[r] = fmaf(in4.x, w0, fmaf(in4.y, w1, fmaf(in4.z, w2, fmaf(in4.w, w3, acc[r]))));
            }
        }
        __syncthreads();
    }

    #pragma unroll
    for (int r = 0; r < 8; ++r) {
        int rg = rbase + rgrp * 8 + r;
        if (rg >= rows) continue;
        if (mode == 0) out[(size_t)rg * 256 + v] = acc[r];
        else {
            int node = rg / 3, m = rg % 3;
            out[(size_t)node * 256 + 64 + v * 3 + m] = acc[r];
        }
    }
}

// ---------------------------------------------------------------------------
extern "C" void kernel_launch(void* const* d_in, const int* in_sizes, int n_in,
                              void* d_out, int out_size) {
    const float* nf    = (const float*)d_in[0];
    const float* attrs = (const float*)d_in[1];
    const float* ea    = (const float*)d_in[2];
    const float* ee    = (const float*)d_in[3];
    const int*   ei    = (const int*)d_in[4];
    const float* Wl10  = (const float*)d_in[5];
    const float* Wl11  = (const float*)d_in[6];
    const float* Wfc1  = (const float*)d_in[7];
    const float* Wfc2  = (const float*)d_in[8];
    const float* Wl20  = (const float*)d_in[9];
    const float* Wl21  = (const float*)d_in[10];
    const float* Wsc0  = (const float*)d_in[11];
    const float* Wsc1  = (const float*)d_in[12];
    float* out = (float*)d_out;

    int n = in_sizes[0] / 256;
    int E = in_sizes[2] / 4;

    // launch 0: degree count (g_deg zero by invariant)
    count_kernel<<<(E + 255) / 256, 256>>>(ei, E);
    // launch 1: scan -> row/cursor, re-zero g_deg
    scan_kernel<<<1, 1024>>>(n);
    // launch 2: edge MLP + packed-record scatter
    scatter_h_kernel<<<(E + 255) / 256, 256>>>(ei, ee, ea, Wfc1, E);
    // launch 3: node pre (y0, y1)
    int pre_nb0 = (n + 31) / 32, pre_nb1 = (3 * n + 31) / 32;
    pre_gemm_kernel<<<pre_nb0 + pre_nb1, 256>>>(nf, Wl10, Wl11, n, pre_nb0);
    // launch 4: aggregation (64-thread block per node)
    agg_kernel<<<n, 64>>>(Wfc2, n);
    // launch 5: node post
    int post_nb0 = (n + 31) / 32, post_nb1 = (3 * n + 31) / 32;
    post_gemm_kernel<<<post_nb0 + post_nb1, 256>>>(nf, attrs, Wl20, Wl21, Wsc0, Wsc1, out, n, post_nb0);
}

// round 14
// speedup vs baseline: 1.0856x; 1.0048x over previous
#include <cuda_runtime.h>
#include <math.h>

#define MAXN 10000
#define MAXE 320000

// Scratch (__device__ globals per allocation-free rule)
__device__ float4 g_y4[MAXN * 64];    // [node][u] = (y0, y1x, y1y, y1z), scale 1/8 folded
__device__ float  g_agg[MAXN * 512];  // reference concat layout, LIN2S (1/64) folded
__device__ float4 g_erec[MAXE * 4];   // packed CSR edge record: [sh | h0..3 | h4..7 | src,pad]
__device__ int    g_deg[MAXN];        // zero-invariant between calls (scan re-zeroes)
__device__ int    g_row[MAXN + 1];
__device__ int    g_cursor[MAXN];

#define INV_SQRT8 0.35355339059327373f
#define INV_SQRT3 0.5773502691896258f
#define LOG2F_C   0.6931471805599453f
#define LIN2S     0.015625f   // 1/(sqrt(32)*sqrt(128))
#define SCN       0.0625f     // 1/sqrt(64*4)

// ---------------------------------------------------------------------------
// Fused launch 0: blocks [0, cb) = degree count; blocks [cb, ...) = node-pre GEMMs.
// (Independent: count touches g_deg; pre writes g_y4.)
__global__ void fused_count_pre_kernel(const int* __restrict__ eidx,
                                       const float* __restrict__ nf,
                                       const float* __restrict__ Wl10,
                                       const float* __restrict__ Wl11,
                                       int E, int n, int cb, int nb0) {
    __shared__ __align__(16) float sIn[32 * 64];
    __shared__ __align__(16) float sW[64 * 64];
    int tid = threadIdx.x;

    if (blockIdx.x < cb) {
        int e = blockIdx.x * 256 + tid;
        if (e < E) atomicAdd(&g_deg[eidx[e]], 1);
        return;
    }

    // ----- node pre GEMM part -----
    int bx = blockIdx.x - cb;
    int v = tid & 63, rgrp = tid >> 6;
    int mode = (bx >= nb0) ? 1 : 0;
    int blk = mode ? (bx - nb0) : bx;
    int rows = mode ? 3 * n : n;
    int rbase = blk * 32;
    const float* W = mode ? Wl11 : Wl10;

    for (int i = tid; i < 4096; i += 256) sW[i] = W[i];
    for (int i = tid; i < 2048; i += 256) {
        int row = i >> 6, k = i & 63;
        int rg = rbase + row;
        float val = 0.f;
        if (rg < rows) {
            if (mode == 0) val = nf[(size_t)rg * 256 + k];
            else {
                int node = rg / 3, m = rg % 3;
                val = nf[(size_t)node * 256 + 64 + k * 3 + m];
            }
        }
        sIn[i] = val;
    }
    __syncthreads();

    float acc[8] = {0.f, 0.f, 0.f, 0.f, 0.f, 0.f, 0.f, 0.f};
    for (int kk = 0; kk < 64; kk += 4) {
        float w0 = sW[(kk + 0) * 64 + v];
        float w1 = sW[(kk + 1) * 64 + v];
        float w2 = sW[(kk + 2) * 64 + v];
        float w3 = sW[(kk + 3) * 64 + v];
        #pragma unroll
        for (int r = 0; r < 8; ++r) {
            const float4 in4 = *(const float4*)(sIn + (rgrp * 8 + r) * 64 + kk);
            acc[r] = fmaf(in4.x, w0, fmaf(in4.y, w1, fmaf(in4.z, w2, fmaf(in4.w, w3, acc[r]))));
        }
    }
    float* gy = (float*)g_y4;
    #pragma unroll
    for (int r = 0; r < 8; ++r) {
        int rg = rbase + rgrp * 8 + r;
        if (rg >= rows) continue;
        float val = acc[r] * 0.125f;
        if (mode == 0) gy[((size_t)rg * 64 + v) * 4 + 0] = val;
        else {
            int node = rg / 3, m = rg % 3;
            gy[((size_t)node * 64 + v) * 4 + 1 + m] = val;
        }
    }
}

// Single-block scan g_deg -> g_row, g_cursor; re-zeroes g_deg for the next call.
__global__ void scan_kernel(int n) {
    __shared__ int part[1024];
    int tid = threadIdx.x;
    int IT = (n + 1023) >> 10;
    int base = tid * IT;
    int degs[16];
    int s = 0;
    for (int i = 0; i < IT; ++i) {
        int idx = base + i;
        degs[i] = (idx < n) ? g_deg[idx] : 0;
        s += degs[i];
    }
    part[tid] = s;
    __syncthreads();
    for (int off = 1; off < 1024; off <<= 1) {
        int v = (tid >= off) ? part[tid - off] : 0;
        __syncthreads();
        part[tid] += v;
        __syncthreads();
    }
    int run = part[tid] - s;
    for (int i = 0; i < IT; ++i) {
        int idx = base + i;
        if (idx < n) {
            g_row[idx] = run;
            g_cursor[idx] = run;
            run += degs[i];
            g_deg[idx] = 0;             // restore zero-invariant
        }
    }
    if (tid == 1023) g_row[n] = part[1023];
}

// Fused: per-edge MLP hidden layer h + CSR scatter of the PACKED 64B record.
__global__ void scatter_h_kernel(const int* __restrict__ eidx,
                                 const float* __restrict__ eemb,
                                 const float* __restrict__ eattr,
                                 const float* __restrict__ Wfc1,
                                 int E) {
    __shared__ float sW1[64];
    int tid = threadIdx.x;
    if (tid < 64) sW1[tid] = Wfc1[tid];
    __syncthreads();
    int e = blockIdx.x * blockDim.x + tid;
    if (e >= E) return;

    int dst = __ldg(eidx + e);
    int src = __ldg(eidx + E + e);
    int pos = atomicAdd(&g_cursor[dst], 1);

    float4 sh = __ldg((const float4*)(eattr + (size_t)e * 4));
    float4 e0 = *(const float4*)(eemb + (size_t)e * 8);
    float4 e1 = *(const float4*)(eemb + (size_t)e * 8 + 4);
    float emb[8] = {e0.x, e0.y, e0.z, e0.w, e1.x, e1.y, e1.z, e1.w};
    float h[8];
    #pragma unroll
    for (int j = 0; j < 8; ++j) {
        float z = 0.f;
        #pragma unroll
        for (int k = 0; k < 8; ++k) z = fmaf(emb[k], sW1[k * 8 + j], z);
        z *= INV_SQRT8;
        float sp = (z > 20.f) ? z : log1pf(__expf(z));
        h[j] = (sp - LOG2F_C) * INV_SQRT8;
    }

    float4* rp = g_erec + (size_t)pos * 4;
    rp[0] = sh;
    rp[1] = make_float4(h[0], h[1], h[2], h[3]);
    rp[2] = make_float4(h[4], h[5], h[6], h[7]);
    rp[3] = make_float4(__int_as_float(src), 0.f, 0.f, 0.f);
}

// ---------------------------------------------------------------------------
// Aggregation v4: 64-thread block per node, 2-edge unrolled loop (2 independent
// src->y4 chains in flight). No smem, no barriers, no atomics.
__global__ void __launch_bounds__(64) agg_kernel(const float* __restrict__ Wfc2, int n) {
    int u = threadIdx.x;
    int node = blockIdx.x;

    float wA[8], wB[8], wC[8], wD[8];
    #pragma unroll
    for (int j = 0; j < 8; ++j) {
        const float* r = Wfc2 + j * 256;
        wA[j] = __ldg(r + u);
        wB[j] = __ldg(r + 64 + u);
        wC[j] = __ldg(r + 128 + u);
        wD[j] = __ldg(r + 192 + u);
    }

    int rs = g_row[node], re = g_row[node + 1];

    float a0 = 0.f, a1 = 0.f, a2 = 0.f, a3 = 0.f, a4 = 0.f, a5 = 0.f, a6 = 0.f, a7 = 0.f;

    int i = rs;
    for (; i + 2 <= re; i += 2) {
        // ---- batch ALL loads for two edges up front (2 independent chains) ----
        const float4* rpA = g_erec + (size_t)i * 4;
        const float4* rpB = rpA + 4;
        float4 shA = __ldg(rpA);
        float4 h0A = __ldg(rpA + 1);
        float4 h1A = __ldg(rpA + 2);
        int srcA = __float_as_int(__ldg((const float*)(rpA + 3)));
        float4 shB = __ldg(rpB);
        float4 h0B = __ldg(rpB + 1);
        float4 h1B = __ldg(rpB + 2);
        int srcB = __float_as_int(__ldg((const float*)(rpB + 3)));
        float4 yA = __ldg(g_y4 + (size_t)srcA * 64 + u);
        float4 yB = __ldg(g_y4 + (size_t)srcB * 64 + u);

        // ---- edge A ----
        {
            float w1 = fmaf(h0A.x, wA[0], fmaf(h0A.y, wA[1], fmaf(h0A.z, wA[2], fmaf(h0A.w, wA[3],
                       fmaf(h1A.x, wA[4], fmaf(h1A.y, wA[5], fmaf(h1A.z, wA[6], h1A.w * wA[7])))))));
            float w2 = fmaf(h0A.x, wB[0], fmaf(h0A.y, wB[1], fmaf(h0A.z, wB[2], fmaf(h0A.w, wB[3],
                       fmaf(h1A.x, wB[4], fmaf(h1A.y, wB[5], fmaf(h1A.z, wB[6], h1A.w * wB[7])))))));
            float w3 = fmaf(h0A.x, wC[0], fmaf(h0A.y, wC[1], fmaf(h0A.z, wC[2], fmaf(h0A.w, wC[3],
                       fmaf(h1A.x, wC[4], fmaf(h1A.y, wC[5], fmaf(h1A.z, wC[6], h1A.w * wC[7])))))));
            float w4 = fmaf(h0A.x, wD[0], fmaf(h0A.y, wD[1], fmaf(h0A.z, wD[2], fmaf(h0A.w, wD[3],
                       fmaf(h1A.x, wD[4], fmaf(h1A.y, wD[5], fmaf(h1A.z, wD[6], h1A.w * wD[7])))))));
            float xs0 = yA.x, x1x = yA.y, x1y = yA.z, x1z = yA.w;
            float dotv = fmaf(x1x, shA.y, fmaf(x1y, shA.z, x1z * shA.w));
            float a2c = w2 * xs0;
            float a3c = w3 * shA.x;
            a0 = fmaf(w1 * xs0, shA.x, a0);
            a1 = fmaf(w4 * INV_SQRT3, dotv, a1);
            a2 = fmaf(a2c, shA.y, a2);
            a3 = fmaf(a2c, shA.z, a3);
            a4 = fmaf(a2c, shA.w, a4);
            a5 = fmaf(a3c, x1x, a5);
            a6 = fmaf(a3c, x1y, a6);
            a7 = fmaf(a3c, x1z, a7);
        }
        // ---- edge B ----
        {
            float w1 = fmaf(h0B.x, wA[0], fmaf(h0B.y, wA[1], fmaf(h0B.z, wA[2], fmaf(h0B.w, wA[3],
                       fmaf(h1B.x, wA[4], fmaf(h1B.y, wA[5], fmaf(h1B.z, wA[6], h1B.w * wA[7])))))));
            float w2 = fmaf(h0B.x, wB[0], fmaf(h0B.y, wB[1], fmaf(h0B.z, wB[2], fmaf(h0B.w, wB[3],
                       fmaf(h1B.x, wB[4], fmaf(h1B.y, wB[5], fmaf(h1B.z, wB[6], h1B.w * wB[7])))))));
            float w3 = fmaf(h0B.x, wC[0], fmaf(h0B.y, wC[1], fmaf(h0B.z, wC[2], fmaf(h0B.w, wC[3],
                       fmaf(h1B.x, wC[4], fmaf(h1B.y, wC[5], fmaf(h1B.z, wC[6], h1B.w * wC[7])))))));
            float w4 = fmaf(h0B.x, wD[0], fmaf(h0B.y, wD[1], fmaf(h0B.z, wD[2], fmaf(h0B.w, wD[3],
                       fmaf(h1B.x, wD[4], fmaf(h1B.y, wD[5], fmaf(h1B.z, wD[6], h1B.w * wD[7])))))));
            float xs0 = yB.x, x1x = yB.y, x1y = yB.z, x1z = yB.w;
            float dotv = fmaf(x1x, shB.y, fmaf(x1y, shB.z, x1z * shB.w));
            float a2c = w2 * xs0;
            float a3c = w3 * shB.x;
            a0 = fmaf(w1 * xs0, shB.x, a0);
            a1 = fmaf(w4 * INV_SQRT3, dotv, a1);
            a2 = fmaf(a2c, shB.y, a2);
            a3 = fmaf(a2c, shB.z, a3);
            a4 = fmaf(a2c, shB.w, a4);
            a5 = fmaf(a3c, x1x, a5);
            a6 = fmaf(a3c, x1y, a6);
            a7 = fmaf(a3c, x1z, a7);
        }
    }
    // tail edge
    if (i < re) {
        const float4* rp = g_erec + (size_t)i * 4;
        float4 sh = __ldg(rp);
        float4 h0 = __ldg(rp + 1);
        float4 h1 = __ldg(rp + 2);
        int src = __float_as_int(__ldg((const float*)(rp + 3)));
        float4 y4 = __ldg(g_y4 + (size_t)src * 64 + u);
        float xs0 = y4.x, x1x = y4.y, x1y = y4.z, x1z = y4.w;
        float w1 = fmaf(h0.x, wA[0], fmaf(h0.y, wA[1], fmaf(h0.z, wA[2], fmaf(h0.w, wA[3],
                   fmaf(h1.x, wA[4], fmaf(h1.y, wA[5], fmaf(h1.z, wA[6], h1.w * wA[7])))))));
        float w2 = fmaf(h0.x, wB[0], fmaf(h0.y, wB[1], fmaf(h0.z, wB[2], fmaf(h0.w, wB[3],
                   fmaf(h1.x, wB[4], fmaf(h1.y, wB[5], fmaf(h1.z, wB[6], h1.w * wB[7])))))));
        float w3 = fmaf(h0.x, wC[0], fmaf(h0.y, wC[1], fmaf(h0.z, wC[2], fmaf(h0.w, wC[3],
                   fmaf(h1.x, wC[4], fmaf(h1.y, wC[5], fmaf(h1.z, wC[6], h1.w * wC[7])))))));
        float w4 = fmaf(h0.x, wD[0], fmaf(h0.y, wD[1], fmaf(h0.z, wD[2], fmaf(h0.w, wD[3],
                   fmaf(h1.x, wD[4], fmaf(h1.y, wD[5], fmaf(h1.z, wD[6], h1.w * wD[7])))))));
        float dotv = fmaf(x1x, sh.y, fmaf(x1y, sh.z, x1z * sh.w));
        float a2c = w2 * xs0;
        float a3c = w3 * sh.x;
        a0 = fmaf(w1 * xs0, sh.x, a0);
        a1 = fmaf(w4 * INV_SQRT3, dotv, a1);
        a2 = fmaf(a2c, sh.y, a2);
        a3 = fmaf(a2c, sh.z, a3);
        a4 = fmaf(a2c, sh.w, a4);
        a5 = fmaf(a3c, x1x, a5);
        a6 = fmaf(a3c, x1y, a6);
        a7 = fmaf(a3c, x1z, a7);
    }

    float* arow = g_agg + (size_t)node * 512;
    arow[u]               = a0 * LIN2S;
    arow[64 + u]          = a1 * LIN2S;
    arow[128 + 3 * u + 0] = a2 * LIN2S;
    arow[128 + 3 * u + 1] = a3 * LIN2S;
    arow[128 + 3 * u + 2] = a4 * LIN2S;
    arow[320 + 3 * u + 0] = a5 * LIN2S;
    arow[320 + 3 * u + 1] = a6 * LIN2S;
    arow[320 + 3 * u + 2] = a7 * LIN2S;
}

// ---------------------------------------------------------------------------
// Node post GEMM, K=384 (3 chunks of 128): [agg_part | attrs (x) x] @ [W_lin2 ; W_sc].
__global__ void post_gemm_kernel(const float* __restrict__ nf,
                                 const float* __restrict__ attrs,
                                 const float* __restrict__ Wl20,
                                 const float* __restrict__ Wl21,
                                 const float* __restrict__ Wsc0,
                                 const float* __restrict__ Wsc1,
                                 float* __restrict__ out,
                                 int n, int nb0) {
    __shared__ __align__(16) float sIn[32 * 128];   // 16 KB
    __shared__ __align__(16) float sW[128 * 64];    // 32 KB
    int tid = threadIdx.x;
    int v = tid & 63, rgrp = tid >> 6;
    int mode = (blockIdx.x >= nb0) ? 1 : 0;
    int blk = mode ? (blockIdx.x - nb0) : blockIdx.x;
    int rows = mode ? 3 * n : n;
    int rbase = blk * 32;
    const float* Wlin = mode ? Wl21 : Wl20;
    const float* Wsc  = mode ? Wsc1 : Wsc0;

    float acc[8] = {0.f, 0.f, 0.f, 0.f, 0.f, 0.f, 0.f, 0.f};

    for (int c = 0; c < 3; ++c) {
        for (int i = tid; i < 8192; i += 256) {
            int kk = i >> 6, vv = i & 63;
            int k = c * 128 + kk;
            float w;
            if (k < 128) w = Wlin[k * 64 + vv];
            else {
                int t2 = k - 128, a = t2 >> 6, uu = t2 & 63;
                w = Wsc[uu * 256 + a * 64 + vv];
            }
            sW[i] = w;
        }
        for (int i = tid; i < 4096; i += 256) {
            int row = i >> 7, kk = i & 127;
            int rg = rbase + row;
            int k = c * 128 + kk;
            float val = 0.f;
            if (rg < rows) {
                if (mode == 0) {
                    if (k < 128) val = g_agg[(size_t)rg * 512 + k];
                    else {
                        int t2 = k - 128, a = t2 >> 6, uu = t2 & 63;
                        val = attrs[(size_t)rg * 4 + a] * nf[(size_t)rg * 256 + uu] * SCN;
                    }
                } else {
                    int node = rg / 3, m = rg % 3;
                    if (k < 128) val = g_agg[(size_t)node * 512 + 128 + k * 3 + m];
                    else {
                        int t2 = k - 128, a = t2 >> 6, uu = t2 & 63;
                        val = attrs[(size_t)node * 4 + a] * nf[(size_t)node * 256 + 64 + uu * 3 + m] * SCN;
                    }
                }
            }
            sIn[i] = val;
        }
        __syncthreads();

        for (int kk = 0; kk < 128; kk += 4) {
            float w0 = sW[(kk + 0) * 64 + v];
            float w1 = sW[(kk + 1) * 64 + v];
            float w2 = sW[(kk + 2) * 64 + v];
            float w3 = sW[(kk + 3) * 64 + v];
            #pragma unroll
            for (int r = 0; r < 8; ++r) {
                const float4 in4 = *(const float4*)(sIn + (rgrp * 8 + r) * 128 + kk);
                acc[r] = fmaf(in4.x, w0, fmaf(in4.y, w1, fmaf(in4.z, w2, fmaf(in4.w, w3, acc[r]))));
            }
        }
        __syncthreads();
    }

    #pragma unroll
    for (int r = 0; r < 8; ++r) {
        int rg = rbase + rgrp * 8 + r;
        if (rg >= rows) continue;
        if (mode == 0) out[(size_t)rg * 256 + v] = acc[r];
        else {
            int node = rg / 3, m = rg % 3;
            out[(size_t)node * 256 + 64 + v * 3 + m] = acc[r];
        }
    }
}

// ---------------------------------------------------------------------------
extern "C" void kernel_launch(void* const* d_in, const int* in_sizes, int n_in,
                              void* d_out, int out_size) {
    const float* nf    = (const float*)d_in[0];
    const float* attrs = (const float*)d_in[1];
    const float* ea    = (const float*)d_in[2];
    const float* ee    = (const float*)d_in[3];
    const int*   ei    = (const int*)d_in[4];
    const float* Wl10  = (const float*)d_in[5];
    const float* Wl11  = (const float*)d_in[6];
    const float* Wfc1  = (const float*)d_in[7];
    const float* Wfc2  = (const float*)d_in[8];
    const float* Wl20  = (const float*)d_in[9];
    const float* Wl21  = (const float*)d_in[10];
    const float* Wsc0  = (const float*)d_in[11];
    const float* Wsc1  = (const float*)d_in[12];
    float* out = (float*)d_out;

    int n = in_sizes[0] / 256;
    int E = in_sizes[2] / 4;

    // launch 0: fused degree count + node-pre GEMMs (independent)
    int cb = (E + 255) / 256;
    int pre_nb0 = (n + 31) / 32, pre_nb1 = (3 * n + 31) / 32;
    fused_count_pre_kernel<<<cb + pre_nb0 + pre_nb1, 256>>>(
        ei, nf, Wl10, Wl11, E, n, cb, pre_nb0);
    // launch 1: scan -> row/cursor, re-zero g_deg
    scan_kernel<<<1, 1024>>>(n);
    // launch 2: edge MLP + packed-record scatter
    scatter_h_kernel<<<(E + 255) / 256, 256>>>(ei, ee, ea, Wfc1, E);
    // launch 3: aggregation (profiled slot)
    agg_kernel<<<n, 64>>>(Wfc2, n);
    // launch 4: node post
    int post_nb0 = (n + 31) / 32, post_nb1 = (3 * n + 31) / 32;
    post_gemm_kernel<<<post_nb0 + post_nb1, 256>>>(nf, attrs, Wl20, Wl21, Wsc0, Wsc1, out, n, post_nb0);
}